// round 2
// baseline (speedup 1.0000x reference)
#include <cuda_runtime.h>
#include <cuda_bf16.h>
#include <stdint.h>

// Problem constants (fixed for this dataset instance)
#define NTOK 4096
#define NEDGE 131072
#define TNUM 8
#define RNUM 16
#define HNUM 8
#define BNUM 21
#define SEEDS 128

// ---------------------------------------------------------------------------
// CSR scratch (device globals — no allocation allowed in kernel_launch).
// Rebuilt deterministically-enough on every launch (zeroed first).
// ---------------------------------------------------------------------------
__device__ int g_count[NTOK];
__device__ int g_rowstart[NTOK + 1];
__device__ int g_cursor[NTOK];
__device__ int g_packed[NEDGE];   // (dst << 4) | rel

// ---------------------------------------------------------------------------
// Bucketize: matches the JAX reference in fp32.
// ---------------------------------------------------------------------------
__device__ __forceinline__ int bucketize(float dt) {
    float s  = (dt > 0.0f) ? 1.0f : ((dt < 0.0f) ? -1.0f : 0.0f);
    float sl = s * log1pf(fabsf(dt) + 1e-6f);
    float c  = fminf(fmaxf(sl, -5.0f), 5.0f);
    float norm = (c + 5.0f) / (10.0f + 1e-9f);
    int idx = (int)floorf(norm * (float)(BNUM - 1));
    idx = idx < 0 ? 0 : idx;
    idx = idx > (BNUM - 1) ? (BNUM - 1) : idx;
    return idx;
}

// ---------------------------------------------------------------------------
// CSR build step 1: zero per-row counters.
// ---------------------------------------------------------------------------
__global__ void zero_kernel() {
    int i = blockIdx.x * blockDim.x + threadIdx.x;
    if (i < NTOK) g_count[i] = 0;
}

// CSR build step 2: histogram edges by src row.
__global__ __launch_bounds__(256) void count_kernel(const int* __restrict__ edge_src) {
    int e = blockIdx.x * blockDim.x + threadIdx.x;
    if (e < NEDGE) atomicAdd(&g_count[edge_src[e]], 1);
}

// CSR build step 3: exclusive scan over 4096 counts (single block, 1024 thr).
__global__ __launch_bounds__(1024) void scan_kernel() {
    __shared__ int sc[1024];
    const int tid  = threadIdx.x;
    const int base = tid * 4;
    int c0 = g_count[base + 0];
    int c1 = g_count[base + 1];
    int c2 = g_count[base + 2];
    int c3 = g_count[base + 3];
    int s = c0 + c1 + c2 + c3;
    sc[tid] = s;
    __syncthreads();
    // Hillis-Steele inclusive scan
    #pragma unroll
    for (int off = 1; off < 1024; off <<= 1) {
        int v = (tid >= off) ? sc[tid - off] : 0;
        __syncthreads();
        sc[tid] += v;
        __syncthreads();
    }
    int excl = sc[tid] - s;
    int p0 = excl;
    int p1 = excl + c0;
    int p2 = p1 + c1;
    int p3 = p2 + c2;
    g_rowstart[base + 0] = p0;  g_cursor[base + 0] = p0;
    g_rowstart[base + 1] = p1;  g_cursor[base + 1] = p1;
    g_rowstart[base + 2] = p2;  g_cursor[base + 2] = p2;
    g_rowstart[base + 3] = p3;  g_cursor[base + 3] = p3;
    if (tid == 1023) g_rowstart[NTOK] = excl + s;
}

// CSR build step 4: scatter packed (dst, rel) into row-sorted order.
__global__ __launch_bounds__(256) void scatter_kernel(
    const int* __restrict__ edge_src,
    const int* __restrict__ edge_dst,
    const int* __restrict__ edge_rel)
{
    int e = blockIdx.x * blockDim.x + threadIdx.x;
    if (e >= NEDGE) return;
    int s = edge_src[e];
    int pos = atomicAdd(&g_cursor[s], 1);
    g_packed[pos] = (edge_dst[e] << 4) | edge_rel[e];
}

// ---------------------------------------------------------------------------
// Fused fill + edge kernel: one block per (i, h) row.
//   1. compute base row (typepair LUT gather + optional temporal bias) in smem
//   2. apply this row's edges via smem atomicAdd (ATOMS — cheap)
//   3. store the finished 16 KB row once, coalesced float4
// ---------------------------------------------------------------------------
__global__ __launch_bounds__(256) void fill_fused_kernel(
    const int*   __restrict__ token_type,
    const float* __restrict__ time_vec,
    const float* __restrict__ typepair_bias,  // (T, T, H)
    const float* __restrict__ temp_bias,      // (B, H)
    const float* __restrict__ adj_rel_bias,   // (R, H)
    float*       __restrict__ out)            // (H, N, N)
{
    const int i = blockIdx.x;   // row index 0..N-1
    const int h = blockIdx.y;   // head 0..7
    const int tid = threadIdx.x;

    __shared__ float row[NTOK];       // 16 KB staging for one output row
    __shared__ float val8[TNUM];
    __shared__ float tb[BNUM];
    __shared__ float relb[RNUM];

    const int tt_i = token_type[i];
    if (tid < TNUM)  val8[tid] = typepair_bias[(tt_i * TNUM + tid) * HNUM + h];
    if (tid < BNUM)  tb[tid]   = temp_bias[tid * HNUM + h];
    if (tid < RNUM)  relb[tid] = adj_rel_bias[tid * HNUM + h];
    __syncthreads();

    const bool  is_seed = (i < SEEDS);
    const float ti      = time_vec[i];

    // Phase 1: compute base row into smem
    #pragma unroll
    for (int j0 = tid * 4; j0 < NTOK; j0 += 256 * 4) {
        const int4 t4 = *reinterpret_cast<const int4*>(token_type + j0);
        float4 v;
        v.x = val8[t4.x];
        v.y = val8[t4.y];
        v.z = val8[t4.z];
        v.w = val8[t4.w];
        if (is_seed) {
            const float4 tv = *reinterpret_cast<const float4*>(time_vec + j0);
            v.x += tb[bucketize(tv.x - ti)];
            v.y += tb[bucketize(tv.y - ti)];
            v.z += tb[bucketize(tv.z - ti)];
            v.w += tb[bucketize(tv.w - ti)];
        }
        *reinterpret_cast<float4*>(row + j0) = v;
    }
    __syncthreads();

    // Phase 2: apply this row's edges (avg 32 per row) via smem atomics
    const int beg = g_rowstart[i];
    const int end = g_rowstart[i + 1];
    for (int e = beg + tid; e < end; e += 256) {
        const int p = g_packed[e];
        atomicAdd(&row[p >> 4], relb[p & 15]);
    }
    __syncthreads();

    // Phase 3: store the finished row, coalesced
    float* __restrict__ orow =
        out + ((size_t)h * NTOK + (size_t)i) * (size_t)NTOK;
    #pragma unroll
    for (int j0 = tid * 4; j0 < NTOK; j0 += 256 * 4) {
        *reinterpret_cast<float4*>(orow + j0) =
            *reinterpret_cast<const float4*>(row + j0);
    }
}

// ---------------------------------------------------------------------------
// kernel_launch
// ---------------------------------------------------------------------------
extern "C" void kernel_launch(void* const* d_in, const int* in_sizes, int n_in,
                              void* d_out, int out_size)
{
    const int*   token_type    = (const int*)  d_in[0];
    const int*   edge_src      = (const int*)  d_in[1];
    const int*   edge_dst      = (const int*)  d_in[2];
    const int*   edge_rel      = (const int*)  d_in[3];
    const float* time_vec      = (const float*)d_in[4];
    const float* adj_rel_bias  = (const float*)d_in[n_in - 3];
    const float* typepair_bias = (const float*)d_in[n_in - 2];
    const float* temp_bias     = (const float*)d_in[n_in - 1];
    float* out = (float*)d_out;

    // CSR build (all tiny, L2-resident)
    zero_kernel<<<(NTOK + 255) / 256, 256>>>();
    count_kernel<<<(NEDGE + 255) / 256, 256>>>(edge_src);
    scan_kernel<<<1, 1024>>>();
    scatter_kernel<<<(NEDGE + 255) / 256, 256>>>(edge_src, edge_dst, edge_rel);

    // Fused fill + edge apply
    dim3 grid_fill(NTOK, HNUM);
    fill_fused_kernel<<<grid_fill, 256>>>(token_type, time_vec, typepair_bias,
                                          temp_bias, adj_rel_bias, out);
}

// round 3
// speedup vs baseline: 1.1569x; 1.1569x over previous
#include <cuda_runtime.h>
#include <cuda_bf16.h>
#include <stdint.h>

#define NTOK 4096
#define NEDGE 131072
#define TNUM 8
#define RNUM 16
#define HNUM 8
#define BNUM 21
#define SEEDS 128
#define CAP 96            // per-row edge-list capacity (avg degree = 32)
#define BMW (NTOK / 32)   // bitmap words per row = 128

// ---------------------------------------------------------------------------
// Device scratch (no allocation allowed)
// ---------------------------------------------------------------------------
__device__ unsigned g_bitmap[NTOK * BMW];   // 2 MB, per-row dst bitmap
__device__ int      g_cursor[NTOK];         // per-row edge count (raw)
__device__ int      g_elist[NTOK * CAP];    // packed (dst<<4)|rel per row
__device__ int      g_overcnt;              // overflow edge count
__device__ int      g_over[NEDGE];          // packed (src<<16)|(dst<<4)|rel

// ---------------------------------------------------------------------------
__device__ __forceinline__ int bucketize(float dt) {
    float s  = (dt > 0.0f) ? 1.0f : ((dt < 0.0f) ? -1.0f : 0.0f);
    float sl = s * log1pf(fabsf(dt) + 1e-6f);
    float c  = fminf(fmaxf(sl, -5.0f), 5.0f);
    float norm = (c + 5.0f) / (10.0f + 1e-9f);
    int idx = (int)floorf(norm * (float)(BNUM - 1));
    idx = idx < 0 ? 0 : idx;
    idx = idx > (BNUM - 1) ? (BNUM - 1) : idx;
    return idx;
}

__device__ __forceinline__ unsigned hash_d(int d) {
    return ((unsigned)d * 2654435761u >> 16) & 255u;
}

// ---------------------------------------------------------------------------
// Zero bitmap + cursors + overflow counter
// ---------------------------------------------------------------------------
__global__ __launch_bounds__(256) void zero_kernel() {
    int i = blockIdx.x * blockDim.x + threadIdx.x;
    int stride = gridDim.x * blockDim.x;
    for (int k = i; k < NTOK * BMW; k += stride) g_bitmap[k] = 0u;
    if (i < NTOK) g_cursor[i] = 0;
    if (i == 0) g_overcnt = 0;
}

// ---------------------------------------------------------------------------
// Build bitmap + per-row edge lists (one pass over edges)
// ---------------------------------------------------------------------------
__global__ __launch_bounds__(256) void build_kernel(
    const int* __restrict__ edge_src,
    const int* __restrict__ edge_dst,
    const int* __restrict__ edge_rel)
{
    int e = blockIdx.x * blockDim.x + threadIdx.x;
    if (e >= NEDGE) return;
    int s = edge_src[e];
    int d = edge_dst[e];
    int r = edge_rel[e];
    atomicOr(&g_bitmap[s * BMW + (d >> 5)], 1u << (d & 31));
    int pos = atomicAdd(&g_cursor[s], 1);
    if (pos < CAP) {
        g_elist[s * CAP + pos] = (d << 4) | r;
    } else {
        int o = atomicAdd(&g_overcnt, 1);
        g_over[o] = (s << 16) | (d << 4) | r;
    }
}

// ---------------------------------------------------------------------------
// Fused fill: one block per (i, h) row. Direct coalesced float4 stores.
// Edge contributions resolved via per-row bitmap + 256-slot smem hash.
// ---------------------------------------------------------------------------
__global__ __launch_bounds__(256) void fill_kernel(
    const int*   __restrict__ token_type,
    const float* __restrict__ time_vec,
    const float* __restrict__ typepair_bias,  // (T, T, H)
    const float* __restrict__ temp_bias,      // (B, H)
    const float* __restrict__ adj_rel_bias,   // (R, H)
    float*       __restrict__ out)            // (H, N, N)
{
    const int i = blockIdx.x;
    const int h = blockIdx.y;
    const int tid = threadIdx.x;

    __shared__ unsigned sbm[BMW];   // 512 B bitmap row
    __shared__ int      hkey[256];
    __shared__ float    hval[256];
    __shared__ float    val8[TNUM];
    __shared__ float    tb[BNUM];
    __shared__ float    relb[RNUM];

    // init
    hkey[tid] = -1;
    hval[tid] = 0.0f;
    if (tid < BMW)  sbm[tid]  = g_bitmap[i * BMW + tid];
    if (tid < TNUM) {
        const int tt_i = token_type[i];
        val8[tid] = typepair_bias[(tt_i * TNUM + tid) * HNUM + h];
    }
    if (tid < BNUM) tb[tid]   = temp_bias[tid * HNUM + h];
    if (tid < RNUM) relb[tid] = adj_rel_bias[tid * HNUM + h];
    __syncthreads();

    // build smem hash from this row's edge list
    const int count = min(g_cursor[i], CAP);
    for (int e = tid; e < count; e += 256) {
        const int p = g_elist[i * CAP + e];
        const int d = p >> 4;
        const float add = relb[p & 15];
        unsigned slot = hash_d(d);
        while (true) {
            int k = hkey[slot];
            if (k == d) { atomicAdd(&hval[slot], add); break; }
            if (k == -1) {
                int old = atomicCAS(&hkey[slot], -1, d);
                if (old == -1 || old == d) { atomicAdd(&hval[slot], add); break; }
            }
            slot = (slot + 1) & 255u;
        }
    }
    __syncthreads();

    const bool  is_seed = (i < SEEDS);
    const float ti      = time_vec[i];

    float* __restrict__ orow =
        out + ((size_t)h * NTOK + (size_t)i) * (size_t)NTOK;

    #pragma unroll
    for (int j0 = tid * 4; j0 < NTOK; j0 += 256 * 4) {
        const int4 t4 = *reinterpret_cast<const int4*>(token_type + j0);
        float4 v;
        v.x = val8[t4.x];
        v.y = val8[t4.y];
        v.z = val8[t4.z];
        v.w = val8[t4.w];
        if (is_seed) {
            const float4 tv = *reinterpret_cast<const float4*>(time_vec + j0);
            v.x += tb[bucketize(tv.x - ti)];
            v.y += tb[bucketize(tv.y - ti)];
            v.z += tb[bucketize(tv.z - ti)];
            v.w += tb[bucketize(tv.w - ti)];
        }
        // rare-path edge contributions: 4 bits from the row bitmap
        const unsigned m = (sbm[j0 >> 5] >> (j0 & 31)) & 0xFu;
        if (m) {
            #pragma unroll
            for (int q = 0; q < 4; q++) {
                if (m & (1u << q)) {
                    const int d = j0 + q;
                    unsigned slot = hash_d(d);
                    float addv = 0.0f;
                    while (true) {
                        int k = hkey[slot];
                        if (k == d)  { addv = hval[slot]; break; }
                        if (k == -1) break;   // entry lives in overflow list
                        slot = (slot + 1) & 255u;
                    }
                    if (q == 0) v.x += addv;
                    else if (q == 1) v.y += addv;
                    else if (q == 2) v.z += addv;
                    else v.w += addv;
                }
            }
        }
        *reinterpret_cast<float4*>(orow + j0) = v;
    }
}

// ---------------------------------------------------------------------------
// Overflow cleanup (normally zero work): global atomics for edges beyond CAP
// ---------------------------------------------------------------------------
__global__ __launch_bounds__(256) void cleanup_kernel(
    const float* __restrict__ adj_rel_bias,
    float*       __restrict__ out)
{
    const int n = g_overcnt;
    const int total = n * HNUM;
    const int stride = gridDim.x * blockDim.x;
    for (int idx = blockIdx.x * blockDim.x + threadIdx.x; idx < total; idx += stride) {
        const int e = idx >> 3;
        const int h = idx & 7;
        const int p = g_over[e];
        const int s = p >> 16;
        const int d = (p >> 4) & 0xFFF;
        const int r = p & 15;
        atomicAdd(out + (size_t)h * NTOK * NTOK + (size_t)s * NTOK + d,
                  adj_rel_bias[r * HNUM + h]);
    }
}

// ---------------------------------------------------------------------------
extern "C" void kernel_launch(void* const* d_in, const int* in_sizes, int n_in,
                              void* d_out, int out_size)
{
    const int*   token_type    = (const int*)  d_in[0];
    const int*   edge_src      = (const int*)  d_in[1];
    const int*   edge_dst      = (const int*)  d_in[2];
    const int*   edge_rel      = (const int*)  d_in[3];
    const float* time_vec      = (const float*)d_in[4];
    const float* adj_rel_bias  = (const float*)d_in[n_in - 3];
    const float* typepair_bias = (const float*)d_in[n_in - 2];
    const float* temp_bias     = (const float*)d_in[n_in - 1];
    float* out = (float*)d_out;

    zero_kernel<<<2048, 256>>>();
    build_kernel<<<(NEDGE + 255) / 256, 256>>>(edge_src, edge_dst, edge_rel);

    dim3 grid_fill(NTOK, HNUM);
    fill_kernel<<<grid_fill, 256>>>(token_type, time_vec, typepair_bias,
                                    temp_bias, adj_rel_bias, out);

    cleanup_kernel<<<64, 256>>>(adj_rel_bias, out);
}

// round 4
// speedup vs baseline: 1.4792x; 1.2786x over previous
#include <cuda_runtime.h>
#include <cuda_bf16.h>
#include <stdint.h>

#define NTOK 4096
#define NEDGE 131072
#define TNUM 8
#define RNUM 16
#define HNUM 8
#define BNUM 21
#define SEEDS 128
#define CAP 96            // per-row edge-list capacity (avg degree = 32, max ~66)

// ---------------------------------------------------------------------------
// Device scratch (no allocation allowed)
// ---------------------------------------------------------------------------
__device__ int g_cursor[NTOK];         // per-row raw edge count
__device__ int g_elist[NTOK * CAP];    // packed (dst << 4) | rel, per row
__device__ int g_overcnt;              // overflow edge count
__device__ int g_over[NEDGE];          // packed (src << 16) | (dst << 4) | rel

// ---------------------------------------------------------------------------
__device__ __forceinline__ int bucketize(float dt) {
    float s  = (dt > 0.0f) ? 1.0f : ((dt < 0.0f) ? -1.0f : 0.0f);
    float sl = s * log1pf(fabsf(dt) + 1e-6f);
    float c  = fminf(fmaxf(sl, -5.0f), 5.0f);
    float norm = (c + 5.0f) / (10.0f + 1e-9f);
    int idx = (int)floorf(norm * (float)(BNUM - 1));
    idx = idx < 0 ? 0 : idx;
    idx = idx > (BNUM - 1) ? (BNUM - 1) : idx;
    return idx;
}

// ---------------------------------------------------------------------------
// Zero cursors + overflow counter (16 KB, trivial)
// ---------------------------------------------------------------------------
__global__ __launch_bounds__(256) void zero_kernel() {
    int i = blockIdx.x * blockDim.x + threadIdx.x;
    if (i < NTOK) g_cursor[i] = 0;
    if (i == 0)   g_overcnt = 0;
}

// ---------------------------------------------------------------------------
// One-pass per-row edge-list build
// ---------------------------------------------------------------------------
__global__ __launch_bounds__(256) void build_kernel(
    const int* __restrict__ edge_src,
    const int* __restrict__ edge_dst,
    const int* __restrict__ edge_rel)
{
    int e = blockIdx.x * blockDim.x + threadIdx.x;
    if (e >= NEDGE) return;
    int s = edge_src[e];
    int d = edge_dst[e];
    int r = edge_rel[e];
    int pos = atomicAdd(&g_cursor[s], 1);
    if (pos < CAP) {
        g_elist[s * CAP + pos] = (d << 4) | r;
    } else {
        int o = atomicAdd(&g_overcnt, 1);
        g_over[o] = (s << 16) | (d << 4) | r;
    }
}

// ---------------------------------------------------------------------------
// Fill kernel: one block per (i, h) row.
//   Phase 1: direct coalesced float4 stores (identical to the 81us R1 loop).
//   Phase 2: apply this row's ~32 edges with atomicAdd into the just-written
//            row — lines are still L2-resident, so these are L2-hit RMWs.
// ---------------------------------------------------------------------------
__global__ __launch_bounds__(256) void fill_kernel(
    const int*   __restrict__ token_type,
    const float* __restrict__ time_vec,
    const float* __restrict__ typepair_bias,  // (T, T, H)
    const float* __restrict__ temp_bias,      // (B, H)
    const float* __restrict__ adj_rel_bias,   // (R, H)
    float*       __restrict__ out)            // (H, N, N)
{
    const int i = blockIdx.x;
    const int h = blockIdx.y;
    const int tid = threadIdx.x;

    __shared__ float val8[TNUM];
    __shared__ float tb[BNUM];
    __shared__ float relb[RNUM];

    if (tid < TNUM) {
        const int tt_i = token_type[i];
        val8[tid] = typepair_bias[(tt_i * TNUM + tid) * HNUM + h];
    }
    if (tid < BNUM) tb[tid]   = temp_bias[tid * HNUM + h];
    if (tid < RNUM) relb[tid] = adj_rel_bias[tid * HNUM + h];
    __syncthreads();

    const bool  is_seed = (i < SEEDS);
    const float ti      = time_vec[i];

    float* __restrict__ orow =
        out + ((size_t)h * NTOK + (size_t)i) * (size_t)NTOK;

    // Phase 1: 4096 elements / (256 thr * 4) = 4 float4 stores per thread
    #pragma unroll
    for (int j0 = tid * 4; j0 < NTOK; j0 += 256 * 4) {
        const int4 t4 = *reinterpret_cast<const int4*>(token_type + j0);
        float4 v;
        v.x = val8[t4.x];
        v.y = val8[t4.y];
        v.z = val8[t4.z];
        v.w = val8[t4.w];
        if (is_seed) {
            const float4 tv = *reinterpret_cast<const float4*>(time_vec + j0);
            v.x += tb[bucketize(tv.x - ti)];
            v.y += tb[bucketize(tv.y - ti)];
            v.z += tb[bucketize(tv.z - ti)];
            v.w += tb[bucketize(tv.w - ti)];
        }
        *reinterpret_cast<float4*>(orow + j0) = v;
    }
    __syncthreads();   // row fully stored (write-through to L2) before RMW

    // Phase 2: this row's edges — L2-hit atomics into the fresh row
    const int count = min(g_cursor[i], CAP);
    for (int e = tid; e < count; e += 256) {
        const int p = g_elist[i * CAP + e];
        atomicAdd(orow + (p >> 4), relb[p & 15]);
    }
}

// ---------------------------------------------------------------------------
// Overflow cleanup (normally zero work)
// ---------------------------------------------------------------------------
__global__ __launch_bounds__(256) void cleanup_kernel(
    const float* __restrict__ adj_rel_bias,
    float*       __restrict__ out)
{
    const int n = g_overcnt;
    const int total = n * HNUM;
    const int stride = gridDim.x * blockDim.x;
    for (int idx = blockIdx.x * blockDim.x + threadIdx.x; idx < total; idx += stride) {
        const int e = idx >> 3;
        const int h = idx & 7;
        const int p = g_over[e];
        const int s = p >> 16;
        const int d = (p >> 4) & 0xFFF;
        const int r = p & 15;
        atomicAdd(out + (size_t)h * NTOK * NTOK + (size_t)s * NTOK + d,
                  adj_rel_bias[r * HNUM + h]);
    }
}

// ---------------------------------------------------------------------------
extern "C" void kernel_launch(void* const* d_in, const int* in_sizes, int n_in,
                              void* d_out, int out_size)
{
    const int*   token_type    = (const int*)  d_in[0];
    const int*   edge_src      = (const int*)  d_in[1];
    const int*   edge_dst      = (const int*)  d_in[2];
    const int*   edge_rel      = (const int*)  d_in[3];
    const float* time_vec      = (const float*)d_in[4];
    const float* adj_rel_bias  = (const float*)d_in[n_in - 3];
    const float* typepair_bias = (const float*)d_in[n_in - 2];
    const float* temp_bias     = (const float*)d_in[n_in - 1];
    float* out = (float*)d_out;

    zero_kernel<<<(NTOK + 255) / 256, 256>>>();
    build_kernel<<<(NEDGE + 255) / 256, 256>>>(edge_src, edge_dst, edge_rel);

    dim3 grid_fill(NTOK, HNUM);
    fill_kernel<<<grid_fill, 256>>>(token_type, time_vec, typepair_bias,
                                    temp_bias, adj_rel_bias, out);

    cleanup_kernel<<<16, 256>>>(adj_rel_bias, out);
}